// round 3
// baseline (speedup 1.0000x reference)
#include <cuda_runtime.h>
#include <cstdint>

#define BATCH   8
#define CH      256
#define HH      80
#define WW      80
#define HW      (HH*WW)          // 6400
#define OC      32
#define GROUPS  4
#define OH      160
#define OW      160
#define OHW     (OH*OW)          // 25600
#define NPAIR   (BATCH*HW/2)     // 25600 float2 pairs

// scratch for conv output: 8*32*6400 floats = 6.55 MB
__device__ float g_off[BATCH * OC * HW];

__device__ __forceinline__ unsigned long long pack2(float a, float b) {
    unsigned long long r;
    asm("mov.b64 %0, {%1, %2};" : "=l"(r) : "f"(a), "f"(b));
    return r;
}

__device__ __forceinline__ unsigned long long ffma2(unsigned long long a,
                                                    unsigned long long b,
                                                    unsigned long long c) {
    unsigned long long d;
    asm("fma.rn.f32x2 %0, %1, %2, %3;" : "=l"(d) : "l"(a), "l"(b), "l"(c));
    return d;
}

// ---------------------------------------------------------------------------
// Kernel 1 (v2): 1x1 conv as register-blocked GEMM.
// Block = 128 threads = 4 warps. Each warp owns an 8-wide output-channel
// group and 32 spatial pairs (lane = pair). Weights live in smem pre-packed
// as (w,w) u64 -> one broadcast LDS.64 per FFMA2, no pack movs in the loop.
// 800 blocks -> 3200 warps -> ~21.6 warps/SM (was 5.4).
// ---------------------------------------------------------------------------
__global__ void __launch_bounds__(128)
conv_off_kernel(const float* __restrict__ x,
                const float* __restrict__ wq,
                const float* __restrict__ bias) {
    __shared__ unsigned long long ws2[CH * OC];   // [c][o] packed (w,w), 64 KB

    int tid = threadIdx.x;
    for (int idx = tid; idx < CH * OC; idx += 128) {
        int c = idx >> 5;
        int o = idx & 31;
        float w = wq[o * CH + c];
        ws2[idx] = pack2(w, w);
    }
    __syncthreads();

    int lane = tid & 31;
    int og   = tid >> 5;                 // o-group: channels [8*og, 8*og+8)
    int pair = blockIdx.x * 32 + lane;   // 0..25599
    int b    = pair / (HW / 2);
    int pp   = pair % (HW / 2);

    const float2* xp = reinterpret_cast<const float2*>(x + (size_t)b * CH * HW) + pp;
    const unsigned long long* wsp = ws2 + og * 8;

    unsigned long long acc[8];
#pragma unroll
    for (int o = 0; o < 8; o++) acc[o] = 0ULL;

#pragma unroll 4
    for (int c = 0; c < CH; c++) {
        float2 xv = __ldg(&xp[c * (HW / 2)]);
        unsigned long long xv2 = pack2(xv.x, xv.y);
        const unsigned long long* wr = wsp + c * OC;
#pragma unroll
        for (int o = 0; o < 8; o++)
            acc[o] = ffma2(xv2, wr[o], acc[o]);
    }

    float* offp = g_off + (size_t)b * OC * HW + pp * 2;
#pragma unroll
    for (int o = 0; o < 8; o++) {
        int oc = og * 8 + o;
        float bo = __ldg(&bias[oc]);
        float lo = __uint_as_float((unsigned)(acc[o] & 0xffffffffULL)) + bo;
        float hi = __uint_as_float((unsigned)(acc[o] >> 32)) + bo;
        *reinterpret_cast<float2*>(offp + (size_t)oc * HW) = make_float2(lo, hi);
    }
}

// ---------------------------------------------------------------------------
// Kernel 2 (v2): bilinear sampling, channel-chunked for MLP=32.
// One thread per (b, gi, oh, ow); 8-channel chunks: 32 taps in flight before
// any FMA. Streaming stores (__stcs) keep the 210MB output stream from
// evicting x (52MB, fits in L2).
// ---------------------------------------------------------------------------
__global__ void __launch_bounds__(256)
sample_kernel(const float* __restrict__ x, float* __restrict__ out) {
    int idx = blockIdx.x * 256 + threadIdx.x;
    int ow = idx % OW;
    int r  = idx / OW;
    int oh = r % OH;  r /= OH;
    int gi = r & 3;
    int b  = r >> 2;

    int h = oh >> 1, i = oh & 1;
    int w = ow >> 1, j = ow & 1;
    int k = gi * 4 + i * 2 + j;

    const float* offp = g_off + (size_t)b * OC * HW + h * WW + w;
    float offx = __ldg(offp + (size_t)k * HW);
    float offy = __ldg(offp + (size_t)(16 + k) * HW);

    float px = (float)w + 0.25f * (offx + (float)(2 * j - 1));
    float py = (float)h + 0.25f * (offy + (float)(2 * i - 1));

    float ix = fminf(fmaxf(px, 0.0f), (float)(WW - 1));
    float iy = fminf(fmaxf(py, 0.0f), (float)(HH - 1));
    float fx = floorf(ix), fy = floorf(iy);
    int x0 = (int)fx, y0 = (int)fy;
    float wx = ix - fx, wy = iy - fy;
    int x1 = min(x0 + 1, WW - 1);
    int y1 = min(y0 + 1, HH - 1);

    float w00 = (1.0f - wy) * (1.0f - wx);
    float w01 = (1.0f - wy) * wx;
    float w10 = wy * (1.0f - wx);
    float w11 = wy * wx;

    int i00 = y0 * WW + x0;
    int i01 = y0 * WW + x1;
    int i10 = y1 * WW + x0;
    int i11 = y1 * WW + x1;

    const float* bp = x + ((size_t)(b * CH + gi * 64)) * HW;
    float* op = out + ((size_t)(b * CH + gi * 64) * OH + oh) * OW + ow;

#pragma unroll 1
    for (int cc = 0; cc < 64; cc += 8) {
        float a00[8], a01[8], a10[8], a11[8];
#pragma unroll
        for (int u = 0; u < 8; u++) {
            const float* p = bp + (size_t)(cc + u) * HW;
            a00[u] = __ldg(p + i00);
            a01[u] = __ldg(p + i01);
            a10[u] = __ldg(p + i10);
            a11[u] = __ldg(p + i11);
        }
#pragma unroll
        for (int u = 0; u < 8; u++) {
            float v = a00[u] * w00;
            v = fmaf(a01[u], w01, v);
            v = fmaf(a10[u], w10, v);
            v = fmaf(a11[u], w11, v);
            __stcs(op + (size_t)(cc + u) * OHW, v);
        }
    }
}

extern "C" void kernel_launch(void* const* d_in, const int* in_sizes, int n_in,
                              void* d_out, int out_size) {
    const float* x    = (const float*)d_in[0];   // [8,256,80,80]
    const float* wq   = (const float*)d_in[1];   // [32,256,1,1]
    const float* bias = (const float*)d_in[2];   // [32]
    float* out = (float*)d_out;                  // [8,256,160,160]

    conv_off_kernel<<<800, 128>>>(x, wq, bias);

    int total = BATCH * GROUPS * OH * OW;        // 819200
    sample_kernel<<<total / 256, 256>>>(x, out);
}

// round 4
// speedup vs baseline: 1.3577x; 1.3577x over previous
#include <cuda_runtime.h>
#include <cstdint>

#define BATCH   8
#define CH      256
#define HH      80
#define WW      80
#define HW      (HH*WW)          // 6400
#define OC      32
#define GROUPS  4
#define OH      160
#define OW      160
#define OHW     (OH*OW)          // 25600

// scratch for conv output: 8*32*6400 floats = 6.55 MB
__device__ float g_off[BATCH * OC * HW];

__device__ __forceinline__ unsigned long long pack2(float a, float b) {
    unsigned long long r;
    asm("mov.b64 %0, {%1, %2};" : "=l"(r) : "f"(a), "f"(b));
    return r;
}

__device__ __forceinline__ unsigned long long ffma2(unsigned long long a,
                                                    unsigned long long b,
                                                    unsigned long long c) {
    unsigned long long d;
    asm("fma.rn.f32x2 %0, %1, %2, %3;" : "=l"(d) : "l"(a), "l"(b), "l"(c));
    return d;
}

// ---------------------------------------------------------------------------
// Kernel 1 (v3): 1x1 conv. Block = 128 thr = 4 warps; warp og owns 8 output
// channels. Thread handles one float4 (4 spatial positions). Per c:
// 1 LDG.128 + 4 broadcast LDS.128 (8 packed (w,w) weights) + 16 FFMA2.
// 400 blocks x 32 lanes x 4 pos = 51200 positions x 8 b? -> 12800 float4 = all.
// ---------------------------------------------------------------------------
__global__ void __launch_bounds__(128)
conv_off_kernel(const float* __restrict__ x,
                const float* __restrict__ wq,
                const float* __restrict__ bias) {
    __shared__ unsigned long long ws2[CH * OC];   // [c][o] packed (w,w), 64 KB

    int tid = threadIdx.x;
    // fill: idx -> o = idx>>8 (coalesced read of wq rows), c = idx&255
    for (int idx = tid; idx < CH * OC; idx += 128) {
        int o = idx >> 8;
        int c = idx & 255;
        float w = __ldg(&wq[o * CH + c]);
        ws2[c * OC + o] = pack2(w, w);
    }
    __syncthreads();

    int lane = tid & 31;
    int og   = tid >> 5;                    // 8 oc per warp
    int q    = blockIdx.x * 32 + lane;      // float4 index, 12800 total
    int b    = q / (HW / 4);
    int qq   = q % (HW / 4);

    const float4* xp = reinterpret_cast<const float4*>(x + (size_t)b * CH * HW) + qq;
    const unsigned long long* wsp = ws2 + og * 8;

    unsigned long long accL[8], accH[8];
#pragma unroll
    for (int o = 0; o < 8; o++) { accL[o] = 0ULL; accH[o] = 0ULL; }

#pragma unroll 4
    for (int c = 0; c < CH; c++) {
        float4 xv = __ldg(&xp[c * (HW / 4)]);
        unsigned long long lo = pack2(xv.x, xv.y);
        unsigned long long hi = pack2(xv.z, xv.w);
        const unsigned long long* wr = wsp + c * OC;
#pragma unroll
        for (int k = 0; k < 4; k++) {
            // LDS.128: two consecutive packed weights
            unsigned long long w0 = wr[2 * k];
            unsigned long long w1 = wr[2 * k + 1];
            accL[2 * k]     = ffma2(lo, w0, accL[2 * k]);
            accH[2 * k]     = ffma2(hi, w0, accH[2 * k]);
            accL[2 * k + 1] = ffma2(lo, w1, accL[2 * k + 1]);
            accH[2 * k + 1] = ffma2(hi, w1, accH[2 * k + 1]);
        }
    }

    float4* offp = reinterpret_cast<float4*>(g_off + (size_t)b * OC * HW) + qq;
#pragma unroll
    for (int o = 0; o < 8; o++) {
        int oc = og * 8 + o;
        float bo = __ldg(&bias[oc]);
        float4 v;
        v.x = __uint_as_float((unsigned)(accL[o] & 0xffffffffULL)) + bo;
        v.y = __uint_as_float((unsigned)(accL[o] >> 32)) + bo;
        v.z = __uint_as_float((unsigned)(accH[o] & 0xffffffffULL)) + bo;
        v.w = __uint_as_float((unsigned)(accH[o] >> 32)) + bo;
        offp[(size_t)oc * (HW / 4)] = v;
    }
}

// ---------------------------------------------------------------------------
// Kernel 2 (v3): tiled bilinear sampling.
// Thread = (b, gi, 2x2 input pixels, 16-channel chunk) -> 4x4 outputs/channel.
// Offsets are ~N(0,0.016): bilinear cells are statically known, so 16 taps
// (4x4 clamped grid, compile-time indices) serve all 16 outputs. Verified per
// thread via wx,wy in [0,1]; generic fallback otherwise (never in practice).
// ---------------------------------------------------------------------------
__global__ void __launch_bounds__(128)
sample_kernel(const float* __restrict__ x, float* __restrict__ out) {
    int t = blockIdx.x * 128 + threadIdx.x;   // 204800 threads
    int wp = t % 40;  int u = t / 40;
    int hp = u % 40;  u /= 40;
    int cchunk = u & 3;  u >>= 2;
    int gi = u & 3;
    int b  = u >> 2;

    int hbase = 2 * hp, wbase = 2 * wp;

    const float* offb = g_off + (size_t)b * OC * HW;

    float wxv[16], wyv[16];
    bool valid = true;
#pragma unroll
    for (int r = 0; r < 4; r++) {
        int hprime = hbase + (r >> 1);
        int i = r & 1;
#pragma unroll
        for (int s = 0; s < 4; s++) {
            int wprime = wbase + (s >> 1);
            int j = s & 1;
            int k = gi * 4 + i * 2 + j;
            const float* op2 = offb + hprime * WW + wprime;
            float offx = __ldg(op2 + (size_t)k * HW);
            float offy = __ldg(op2 + (size_t)(16 + k) * HW);
            float px = (float)wprime + 0.25f * (offx + (float)(2 * j - 1));
            float py = (float)hprime + 0.25f * (offy + (float)(2 * i - 1));
            float ix = fminf(fmaxf(px, 0.0f), (float)(WW - 1));
            float iy = fminf(fmaxf(py, 0.0f), (float)(HH - 1));
            int tx0 = (s >> 1) + (s & 1);
            int ty0 = (r >> 1) + (r & 1);
            float wx = ix - (float)(wbase - 1 + tx0);
            float wy = iy - (float)(hbase - 1 + ty0);
            wxv[r * 4 + s] = wx;
            wyv[r * 4 + s] = wy;
            valid = valid && (wx >= 0.0f) && (wx <= 1.0f)
                          && (wy >= 0.0f) && (wy <= 1.0f);
        }
    }

    int c0 = cchunk * 16;
    const float* bp = x + (size_t)(b * CH + gi * 64 + c0) * HW;
    // output row/col base for this tile
    int ohb = 4 * hp;
    int owb = 4 * wp;
    float* opb = out + (size_t)(b * CH + gi * 64 + c0) * OHW;

    if (valid) {
        int toff[16];
#pragma unroll
        for (int ty = 0; ty < 4; ty++) {
            int rr = min(max(hbase - 1 + ty, 0), HH - 1) * WW;
#pragma unroll
            for (int tx = 0; tx < 4; tx++) {
                int cc = min(max(wbase - 1 + tx, 0), WW - 1);
                toff[ty * 4 + tx] = rr + cc;
            }
        }

#pragma unroll 2
        for (int c = 0; c < 16; c++) {
            const float* pc = bp + (size_t)c * HW;
            float tv[16];
#pragma unroll
            for (int m = 0; m < 16; m++) tv[m] = __ldg(pc + toff[m]);

            float* oc = opb + (size_t)c * OHW;
#pragma unroll
            for (int r = 0; r < 4; r++) {
                float vv[4];
#pragma unroll
                for (int s = 0; s < 4; s++) {
                    const int tx0 = (s >> 1) + (s & 1);
                    const int ty0 = (r >> 1) + (r & 1);
                    float a0 = tv[ty0 * 4 + tx0];
                    float a1 = tv[ty0 * 4 + tx0 + 1];
                    float a2 = tv[(ty0 + 1) * 4 + tx0];
                    float a3 = tv[(ty0 + 1) * 4 + tx0 + 1];
                    float wx = wxv[r * 4 + s];
                    float wy = wyv[r * 4 + s];
                    float h0 = fmaf(wx, a1 - a0, a0);
                    float h1 = fmaf(wx, a3 - a2, a2);
                    vv[s] = fmaf(wy, h1 - h0, h0);
                }
                float4 v4 = make_float4(vv[0], vv[1], vv[2], vv[3]);
                *reinterpret_cast<float4*>(oc + (size_t)(ohb + r) * OW + owb) = v4;
            }
        }
    } else {
        // Generic fallback (statistically never taken; exact reference math).
        for (int c = 0; c < 16; c++) {
            const float* pc = bp + (size_t)c * HW;
            float* oc = opb + (size_t)c * OHW;
#pragma unroll
            for (int r = 0; r < 4; r++) {
                float vv[4];
#pragma unroll
                for (int s = 0; s < 4; s++) {
                    int hprime = hbase + (r >> 1);
                    int i = r & 1;
                    int wprime = wbase + (s >> 1);
                    int j = s & 1;
                    int k = gi * 4 + i * 2 + j;
                    const float* op2 = offb + hprime * WW + wprime;
                    float offx = __ldg(op2 + (size_t)k * HW);
                    float offy = __ldg(op2 + (size_t)(16 + k) * HW);
                    float px = (float)wprime + 0.25f * (offx + (float)(2 * j - 1));
                    float py = (float)hprime + 0.25f * (offy + (float)(2 * i - 1));
                    float ix = fminf(fmaxf(px, 0.0f), (float)(WW - 1));
                    float iy = fminf(fmaxf(py, 0.0f), (float)(HH - 1));
                    float fx = floorf(ix), fy = floorf(iy);
                    int x0 = (int)fx, y0 = (int)fy;
                    float wx = ix - fx, wy = iy - fy;
                    int x1 = min(x0 + 1, WW - 1);
                    int y1 = min(y0 + 1, HH - 1);
                    float a0 = __ldg(pc + y0 * WW + x0);
                    float a1 = __ldg(pc + y0 * WW + x1);
                    float a2 = __ldg(pc + y1 * WW + x0);
                    float a3 = __ldg(pc + y1 * WW + x1);
                    float h0 = fmaf(wx, a1 - a0, a0);
                    float h1 = fmaf(wx, a3 - a2, a2);
                    vv[s] = fmaf(wy, h1 - h0, h0);
                }
                float4 v4 = make_float4(vv[0], vv[1], vv[2], vv[3]);
                *reinterpret_cast<float4*>(oc + (size_t)(ohb + r) * OW + owb) = v4;
            }
        }
    }
}

extern "C" void kernel_launch(void* const* d_in, const int* in_sizes, int n_in,
                              void* d_out, int out_size) {
    const float* x    = (const float*)d_in[0];   // [8,256,80,80]
    const float* wq   = (const float*)d_in[1];   // [32,256,1,1]
    const float* bias = (const float*)d_in[2];   // [32]
    float* out = (float*)d_out;                  // [8,256,160,160]

    conv_off_kernel<<<400, 128>>>(x, wq, bias);
    sample_kernel<<<1600, 128>>>(x, out);
}

// round 5
// speedup vs baseline: 1.5287x; 1.1260x over previous
#include <cuda_runtime.h>
#include <cstdint>

#define BATCH   8
#define CH      256
#define HH      80
#define WW      80
#define HW      (HH*WW)          // 6400
#define OC      32
#define GROUPS  4
#define OH      160
#define OW      160
#define OHW     (OH*OW)          // 25600

// scratch for conv output: 8*32*6400 floats = 6.55 MB
__device__ float g_off[BATCH * OC * HW];

__device__ __forceinline__ unsigned long long pack2(float a, float b) {
    unsigned long long r;
    asm("mov.b64 %0, {%1, %2};" : "=l"(r) : "f"(a), "f"(b));
    return r;
}

__device__ __forceinline__ unsigned long long ffma2(unsigned long long a,
                                                    unsigned long long b,
                                                    unsigned long long c) {
    unsigned long long d;
    asm("fma.rn.f32x2 %0, %1, %2, %3;" : "=l"(d) : "l"(a), "l"(b), "l"(c));
    return d;
}

// ---------------------------------------------------------------------------
// Kernel 1 (v4): 1x1 conv. 400 blocks x 256 thr = 3200 warps.
// Warp = 4 output channels x 128 spatial positions (lane = float4).
// Explicit 4-deep software-pipelined x prefetch; weights as packed (w,w)
// u64 in smem -> 2 LDS.128 per c. Per-4c body: 4 LDG.128 + 8 LDS.128 +
// 32 FFMA2 ~= the fma-pipe floor (12.6us chip-wide).
// ---------------------------------------------------------------------------
__global__ void __launch_bounds__(256)
conv_off_kernel(const float* __restrict__ x,
                const float* __restrict__ wq,
                const float* __restrict__ bias) {
    __shared__ unsigned long long ws2[CH * OC];   // [c][o] packed (w,w), 64 KB

    int tid = threadIdx.x;
    for (int idx = tid; idx < CH * OC; idx += 256) {
        int o = idx >> 8;          // coalesced over c
        int c = idx & 255;
        float w = __ldg(&wq[o * CH + c]);
        ws2[c * OC + o] = pack2(w, w);
    }
    __syncthreads();

    int lane = tid & 31;
    int gw   = blockIdx.x * 8 + (tid >> 5);   // 0..3199
    int og4  = gw & 7;                        // 4-oc group
    int posw = gw >> 3;                       // 0..399
    int q    = posw * 32 + lane;              // float4 index, 12800 total
    int b    = q / (HW / 4);
    int qq   = q % (HW / 4);

    const float4* xp = reinterpret_cast<const float4*>(x + (size_t)b * CH * HW) + qq;
    const unsigned long long* wsp = ws2 + og4 * 4;

    unsigned long long accL[4], accH[4];
#pragma unroll
    for (int o = 0; o < 4; o++) { accL[o] = 0ULL; accH[o] = 0ULL; }

    // 4-deep prefetch ring
    float4 xv[4];
#pragma unroll
    for (int k = 0; k < 4; k++)
        xv[k] = __ldg(&xp[k * (HW / 4)]);

#pragma unroll 1
    for (int c = 0; c < CH; c += 4) {
#pragma unroll
        for (int k = 0; k < 4; k++) {
            int cn = c + 4 + k;
            cn = (cn < CH) ? cn : (CH - 1);          // harmless dup load at tail
            float4 nxt = __ldg(&xp[cn * (HW / 4)]);

            unsigned long long lo = pack2(xv[k].x, xv[k].y);
            unsigned long long hi = pack2(xv[k].z, xv[k].w);
            const unsigned long long* wr = wsp + (c + k) * OC;
            unsigned long long w0 = wr[0];
            unsigned long long w1 = wr[1];
            unsigned long long w2 = wr[2];
            unsigned long long w3 = wr[3];
            accL[0] = ffma2(lo, w0, accL[0]);
            accH[0] = ffma2(hi, w0, accH[0]);
            accL[1] = ffma2(lo, w1, accL[1]);
            accH[1] = ffma2(hi, w1, accH[1]);
            accL[2] = ffma2(lo, w2, accL[2]);
            accH[2] = ffma2(hi, w2, accH[2]);
            accL[3] = ffma2(lo, w3, accL[3]);
            accH[3] = ffma2(hi, w3, accH[3]);

            xv[k] = nxt;
        }
    }

    float4* offp = reinterpret_cast<float4*>(g_off + (size_t)b * OC * HW) + qq;
#pragma unroll
    for (int o = 0; o < 4; o++) {
        int oc = og4 * 4 + o;
        float bo = __ldg(&bias[oc]);
        float4 v;
        v.x = __uint_as_float((unsigned)(accL[o] & 0xffffffffULL)) + bo;
        v.y = __uint_as_float((unsigned)(accL[o] >> 32)) + bo;
        v.z = __uint_as_float((unsigned)(accH[o] & 0xffffffffULL)) + bo;
        v.w = __uint_as_float((unsigned)(accH[o] >> 32)) + bo;
        offp[(size_t)oc * (HW / 4)] = v;
    }
}

// ---------------------------------------------------------------------------
// Kernel 2 (v4): tiled bilinear sampling, register-dieted.
// Thread = (b, gi, 2x2 input pixels, 16-channel chunk) -> 4x4 outputs/channel;
// 16 statically-indexed taps serve all 16 outputs. Validity checked exactly;
// generic fallback lives in a __noinline__ function so its registers don't
// inflate the hot path. launch_bounds(128,4) caps regs at 128 (occ 50%).
// ---------------------------------------------------------------------------
__device__ __noinline__ void sample_fallback(
    const float* __restrict__ offb, const float* __restrict__ bp,
    float* __restrict__ opb, int gi, int hbase, int wbase, int ohb, int owb)
{
    for (int c = 0; c < 16; c++) {
        const float* pc = bp + (size_t)c * HW;
        float* oc = opb + (size_t)c * OHW;
        for (int r = 0; r < 4; r++) {
            float vv[4];
            for (int s = 0; s < 4; s++) {
                int hprime = hbase + (r >> 1);
                int i = r & 1;
                int wprime = wbase + (s >> 1);
                int j = s & 1;
                int k = gi * 4 + i * 2 + j;
                const float* op2 = offb + hprime * WW + wprime;
                float offx = __ldg(op2 + (size_t)k * HW);
                float offy = __ldg(op2 + (size_t)(16 + k) * HW);
                float px = (float)wprime + 0.25f * (offx + (float)(2 * j - 1));
                float py = (float)hprime + 0.25f * (offy + (float)(2 * i - 1));
                float ix = fminf(fmaxf(px, 0.0f), (float)(WW - 1));
                float iy = fminf(fmaxf(py, 0.0f), (float)(HH - 1));
                float fx = floorf(ix), fy = floorf(iy);
                int x0 = (int)fx, y0 = (int)fy;
                float wx = ix - fx, wy = iy - fy;
                int x1 = min(x0 + 1, WW - 1);
                int y1 = min(y0 + 1, HH - 1);
                float a0 = __ldg(pc + y0 * WW + x0);
                float a1 = __ldg(pc + y0 * WW + x1);
                float a2 = __ldg(pc + y1 * WW + x0);
                float a3 = __ldg(pc + y1 * WW + x1);
                float h0 = fmaf(wx, a1 - a0, a0);
                float h1 = fmaf(wx, a3 - a2, a2);
                vv[s] = fmaf(wy, h1 - h0, h0);
            }
            float4 v4 = make_float4(vv[0], vv[1], vv[2], vv[3]);
            *reinterpret_cast<float4*>(oc + (size_t)(ohb + r) * OW + owb) = v4;
        }
    }
}

__global__ void __launch_bounds__(128, 4)
sample_kernel(const float* __restrict__ x, float* __restrict__ out) {
    int t = blockIdx.x * 128 + threadIdx.x;   // 204800 threads
    int wp = t % 40;  int u = t / 40;
    int hp = u % 40;  u /= 40;
    int cchunk = u & 3;  u >>= 2;
    int gi = u & 3;
    int b  = u >> 2;

    int hbase = 2 * hp, wbase = 2 * wp;

    const float* offb = g_off + (size_t)b * OC * HW;

    float wxv[16], wyv[16];
    bool valid = true;
#pragma unroll
    for (int r = 0; r < 4; r++) {
        int hprime = hbase + (r >> 1);
        int i = r & 1;
#pragma unroll
        for (int s = 0; s < 4; s++) {
            int wprime = wbase + (s >> 1);
            int j = s & 1;
            int k = gi * 4 + i * 2 + j;
            const float* op2 = offb + hprime * WW + wprime;
            float offx = __ldg(op2 + (size_t)k * HW);
            float offy = __ldg(op2 + (size_t)(16 + k) * HW);
            float px = (float)wprime + 0.25f * (offx + (float)(2 * j - 1));
            float py = (float)hprime + 0.25f * (offy + (float)(2 * i - 1));
            float ix = fminf(fmaxf(px, 0.0f), (float)(WW - 1));
            float iy = fminf(fmaxf(py, 0.0f), (float)(HH - 1));
            int tx0 = (s >> 1) + (s & 1);
            int ty0 = (r >> 1) + (r & 1);
            float wx = ix - (float)(wbase - 1 + tx0);
            float wy = iy - (float)(hbase - 1 + ty0);
            wxv[r * 4 + s] = wx;
            wyv[r * 4 + s] = wy;
            valid = valid && (wx >= 0.0f) && (wx <= 1.0f)
                          && (wy >= 0.0f) && (wy <= 1.0f);
        }
    }

    int c0 = cchunk * 16;
    const float* bp = x + (size_t)(b * CH + gi * 64 + c0) * HW;
    int ohb = 4 * hp;
    int owb = 4 * wp;
    float* opb = out + (size_t)(b * CH + gi * 64 + c0) * OHW;

    if (!valid) {
        sample_fallback(offb, bp, opb, gi, hbase, wbase, ohb, owb);
        return;
    }

    // clamped tap rows/cols (8 ints instead of 16 offsets)
    int rowo[4], colo[4];
#pragma unroll
    for (int tq = 0; tq < 4; tq++) {
        rowo[tq] = min(max(hbase - 1 + tq, 0), HH - 1) * WW;
        colo[tq] = min(max(wbase - 1 + tq, 0), WW - 1);
    }

#pragma unroll 1
    for (int c = 0; c < 16; c++) {
        const float* pc = bp + (size_t)c * HW;
        float tv[16];
#pragma unroll
        for (int ty = 0; ty < 4; ty++)
#pragma unroll
            for (int tx = 0; tx < 4; tx++)
                tv[ty * 4 + tx] = __ldg(pc + rowo[ty] + colo[tx]);

        float* oc = opb + (size_t)c * OHW;
#pragma unroll
        for (int r = 0; r < 4; r++) {
            float vv[4];
#pragma unroll
            for (int s = 0; s < 4; s++) {
                const int tx0 = (s >> 1) + (s & 1);
                const int ty0 = (r >> 1) + (r & 1);
                float a0 = tv[ty0 * 4 + tx0];
                float a1 = tv[ty0 * 4 + tx0 + 1];
                float a2 = tv[(ty0 + 1) * 4 + tx0];
                float a3 = tv[(ty0 + 1) * 4 + tx0 + 1];
                float wx = wxv[r * 4 + s];
                float wy = wyv[r * 4 + s];
                float h0 = fmaf(wx, a1 - a0, a0);
                float h1 = fmaf(wx, a3 - a2, a2);
                vv[s] = fmaf(wy, h1 - h0, h0);
            }
            float4 v4 = make_float4(vv[0], vv[1], vv[2], vv[3]);
            *reinterpret_cast<float4*>(oc + (size_t)(ohb + r) * OW + owb) = v4;
        }
    }
}

extern "C" void kernel_launch(void* const* d_in, const int* in_sizes, int n_in,
                              void* d_out, int out_size) {
    const float* x    = (const float*)d_in[0];   // [8,256,80,80]
    const float* wq   = (const float*)d_in[1];   // [32,256,1,1]
    const float* bias = (const float*)d_in[2];   // [32]
    float* out = (float*)d_out;                  // [8,256,160,160]

    conv_off_kernel<<<400, 256>>>(x, wq, bias);
    sample_kernel<<<1600, 128>>>(x, out);
}

// round 6
// speedup vs baseline: 1.9380x; 1.2677x over previous
#include <cuda_runtime.h>
#include <cstdint>

#define BATCH   8
#define CH      256
#define HH      80
#define WW      80
#define HW      (HH*WW)          // 6400
#define OC      32
#define GROUPS  4
#define OH      160
#define OW      160
#define OHW     (OH*OW)          // 25600

#define SC      16               // channels per conv stage
#define NSTAGE  (CH/SC)          // 16

// scratch for conv output: 8*32*6400 floats = 6.55 MB
__device__ float g_off[BATCH * OC * HW];

__device__ __forceinline__ unsigned long long pack2(float a, float b) {
    unsigned long long r;
    asm("mov.b64 %0, {%1, %2};" : "=l"(r) : "f"(a), "f"(b));
    return r;
}

__device__ __forceinline__ unsigned long long ffma2(unsigned long long a,
                                                    unsigned long long b,
                                                    unsigned long long c) {
    unsigned long long d;
    asm("fma.rn.f32x2 %0, %1, %2, %3;" : "=l"(d) : "l"(a), "l"(b), "l"(c));
    return d;
}

// ---------------------------------------------------------------------------
// Kernel 1 (v6): 1x1 conv, smem-staged x (read-once from L2).
// Block = 256 thr = 8 warps, all sharing the SAME 32 float4 positions.
// Warp og computes oc [4*og, 4*og+4). x staged via double-buffered smem
// (16 ch/stage, 8KB/buf); weights unpacked in smem (32KB). Total 48KB.
// Per c per warp: 1 LDS.128 (x) + 1 LDS.128 (w bcast) + packs + 8 FFMA2.
// ---------------------------------------------------------------------------
__global__ void __launch_bounds__(256)
conv_off_kernel(const float* __restrict__ x,
                const float* __restrict__ wq,
                const float* __restrict__ bias) {
    __shared__ float  ws[CH * OC];          // [c][o], 32 KB
    __shared__ float4 xs[2][SC][32];        // 2 x 8 KB

    int tid = threadIdx.x;
    for (int idx = tid; idx < CH * OC; idx += 256) {
        int o = idx >> 8;                   // coalesced over c
        int c = idx & 255;
        ws[c * OC + o] = __ldg(&wq[o * CH + c]);
    }

    int b   = blockIdx.x / 50;              // 400 blocks = 8 b x 50
    int qq0 = (blockIdx.x % 50) * 32;       // float4 base within channel
    const float4* xb = reinterpret_cast<const float4*>(x + (size_t)b * CH * HW);

    // stage loader: 512 float4 per stage; thread loads items tid and tid+256.
    // item i: c_local = i>>5 (0..15), q = i&31 -> one 512B row per warp.
    int c_l0 = tid >> 5;                    // 0..7
    int q0   = tid & 31;

    // prologue: stage 0
    float4 r0 = __ldg(&xb[(size_t)(c_l0)     * (HW / 4) + qq0 + q0]);
    float4 r1 = __ldg(&xb[(size_t)(c_l0 + 8) * (HW / 4) + qq0 + q0]);
    xs[0][c_l0][q0]     = r0;
    xs[0][c_l0 + 8][q0] = r1;
    __syncthreads();                        // covers ws fill + stage 0

    int lane = tid & 31;
    int og   = tid >> 5;                    // 4 oc per warp
    const float* wso = ws + og * 4;

    unsigned long long accL[4], accH[4];
#pragma unroll
    for (int o = 0; o < 4; o++) { accL[o] = 0ULL; accH[o] = 0ULL; }

#pragma unroll 1
    for (int st = 0; st < NSTAGE; st++) {
        int cb  = st * SC;
        int buf = st & 1;

        if (st + 1 < NSTAGE) {
            r0 = __ldg(&xb[(size_t)(cb + SC + c_l0)     * (HW / 4) + qq0 + q0]);
            r1 = __ldg(&xb[(size_t)(cb + SC + c_l0 + 8) * (HW / 4) + qq0 + q0]);
        }

#pragma unroll
        for (int cl = 0; cl < SC; cl++) {
            float4 xv = xs[buf][cl][lane];
            unsigned long long lo = pack2(xv.x, xv.y);
            unsigned long long hi = pack2(xv.z, xv.w);
            // broadcast LDS.128: 4 weights for this warp's oc, 16B aligned
            float4 w4 = *reinterpret_cast<const float4*>(wso + (cb + cl) * OC);
            unsigned long long pw0 = pack2(w4.x, w4.x);
            unsigned long long pw1 = pack2(w4.y, w4.y);
            unsigned long long pw2 = pack2(w4.z, w4.z);
            unsigned long long pw3 = pack2(w4.w, w4.w);
            accL[0] = ffma2(lo, pw0, accL[0]);
            accH[0] = ffma2(hi, pw0, accH[0]);
            accL[1] = ffma2(lo, pw1, accL[1]);
            accH[1] = ffma2(hi, pw1, accH[1]);
            accL[2] = ffma2(lo, pw2, accL[2]);
            accH[2] = ffma2(hi, pw2, accH[2]);
            accL[3] = ffma2(lo, pw3, accL[3]);
            accH[3] = ffma2(hi, pw3, accH[3]);
        }

        __syncthreads();                    // all warps done reading buf^1 (prev stage)
        if (st + 1 < NSTAGE) {
            xs[buf ^ 1][c_l0][q0]     = r0;
            xs[buf ^ 1][c_l0 + 8][q0] = r1;
            __syncthreads();                // next buffer ready
        }
    }

    float4* offp = reinterpret_cast<float4*>(g_off + (size_t)b * OC * HW);
#pragma unroll
    for (int o = 0; o < 4; o++) {
        int oc = og * 4 + o;
        float bo = __ldg(&bias[oc]);
        float4 v;
        v.x = __uint_as_float((unsigned)(accL[o] & 0xffffffffULL)) + bo;
        v.y = __uint_as_float((unsigned)(accL[o] >> 32)) + bo;
        v.z = __uint_as_float((unsigned)(accH[o] & 0xffffffffULL)) + bo;
        v.w = __uint_as_float((unsigned)(accH[o] >> 32)) + bo;
        offp[(size_t)oc * (HW / 4) + qq0 + lane] = v;
    }
}

// ---------------------------------------------------------------------------
// Kernel 2 (v6): tiled bilinear sampling; per-output weights live in smem so
// the hot loop fits in ~84 regs -> 24 warps/SM. Thread = (b, gi, 2x2 input
// pixels, 16-ch chunk) -> 4x4 outputs/channel from 16 static taps.
// ---------------------------------------------------------------------------
__device__ __noinline__ void sample_fallback(
    const float* __restrict__ offb, const float* __restrict__ bp,
    float* __restrict__ opb, int gi, int hbase, int wbase, int ohb, int owb)
{
    for (int c = 0; c < 16; c++) {
        const float* pc = bp + (size_t)c * HW;
        float* oc = opb + (size_t)c * OHW;
        for (int r = 0; r < 4; r++) {
            float vv[4];
            for (int s = 0; s < 4; s++) {
                int hprime = hbase + (r >> 1);
                int i = r & 1;
                int wprime = wbase + (s >> 1);
                int j = s & 1;
                int k = gi * 4 + i * 2 + j;
                const float* op2 = offb + hprime * WW + wprime;
                float offx = __ldg(op2 + (size_t)k * HW);
                float offy = __ldg(op2 + (size_t)(16 + k) * HW);
                float px = (float)wprime + 0.25f * (offx + (float)(2 * j - 1));
                float py = (float)hprime + 0.25f * (offy + (float)(2 * i - 1));
                float ix = fminf(fmaxf(px, 0.0f), (float)(WW - 1));
                float iy = fminf(fmaxf(py, 0.0f), (float)(HH - 1));
                float fx = floorf(ix), fy = floorf(iy);
                int x0 = (int)fx, y0 = (int)fy;
                float wx = ix - fx, wy = iy - fy;
                int x1 = min(x0 + 1, WW - 1);
                int y1 = min(y0 + 1, HH - 1);
                float a0 = __ldg(pc + y0 * WW + x0);
                float a1 = __ldg(pc + y0 * WW + x1);
                float a2 = __ldg(pc + y1 * WW + x0);
                float a3 = __ldg(pc + y1 * WW + x1);
                float h0 = fmaf(wx, a1 - a0, a0);
                float h1 = fmaf(wx, a3 - a2, a2);
                vv[s] = fmaf(wy, h1 - h0, h0);
            }
            float4 v4 = make_float4(vv[0], vv[1], vv[2], vv[3]);
            *reinterpret_cast<float4*>(oc + (size_t)(ohb + r) * OW + owb) = v4;
        }
    }
}

__global__ void __launch_bounds__(128, 6)
sample_kernel(const float* __restrict__ x, float* __restrict__ out) {
    __shared__ float swx[16][128];
    __shared__ float swy[16][128];

    int tid = threadIdx.x;
    int t = blockIdx.x * 128 + tid;           // 204800 threads
    int wp = t % 40;  int u = t / 40;
    int hp = u % 40;  u /= 40;
    int cchunk = u & 3;  u >>= 2;
    int gi = u & 3;
    int b  = u >> 2;

    int hbase = 2 * hp, wbase = 2 * wp;

    const float* offb = g_off + (size_t)b * OC * HW;

    bool valid = true;
#pragma unroll
    for (int r = 0; r < 4; r++) {
        int hprime = hbase + (r >> 1);
        int i = r & 1;
#pragma unroll
        for (int s = 0; s < 4; s++) {
            int wprime = wbase + (s >> 1);
            int j = s & 1;
            int k = gi * 4 + i * 2 + j;
            const float* op2 = offb + hprime * WW + wprime;
            float offx = __ldg(op2 + (size_t)k * HW);
            float offy = __ldg(op2 + (size_t)(16 + k) * HW);
            float px = (float)wprime + 0.25f * (offx + (float)(2 * j - 1));
            float py = (float)hprime + 0.25f * (offy + (float)(2 * i - 1));
            float ix = fminf(fmaxf(px, 0.0f), (float)(WW - 1));
            float iy = fminf(fmaxf(py, 0.0f), (float)(HH - 1));
            int tx0 = (s >> 1) + (s & 1);
            int ty0 = (r >> 1) + (r & 1);
            float wx = ix - (float)(wbase - 1 + tx0);
            float wy = iy - (float)(hbase - 1 + ty0);
            swx[r * 4 + s][tid] = wx;          // per-thread column: no sync needed
            swy[r * 4 + s][tid] = wy;
            valid = valid && (wx >= 0.0f) && (wx <= 1.0f)
                          && (wy >= 0.0f) && (wy <= 1.0f);
        }
    }

    int c0 = cchunk * 16;
    const float* bp = x + (size_t)(b * CH + gi * 64 + c0) * HW;
    int ohb = 4 * hp;
    int owb = 4 * wp;
    float* opb = out + (size_t)(b * CH + gi * 64 + c0) * OHW;

    if (!valid) {
        sample_fallback(offb, bp, opb, gi, hbase, wbase, ohb, owb);
        return;
    }

    int rowo[4], colo[4];
#pragma unroll
    for (int tq = 0; tq < 4; tq++) {
        rowo[tq] = min(max(hbase - 1 + tq, 0), HH - 1) * WW;
        colo[tq] = min(max(wbase - 1 + tq, 0), WW - 1);
    }

#pragma unroll 1
    for (int c = 0; c < 16; c++) {
        const float* pc = bp + (size_t)c * HW;
        float tv[16];
#pragma unroll
        for (int ty = 0; ty < 4; ty++)
#pragma unroll
            for (int tx = 0; tx < 4; tx++)
                tv[ty * 4 + tx] = __ldg(pc + rowo[ty] + colo[tx]);

        float* oc = opb + (size_t)c * OHW;
#pragma unroll
        for (int r = 0; r < 4; r++) {
            float vv[4];
#pragma unroll
            for (int s = 0; s < 4; s++) {
                const int tx0 = (s >> 1) + (s & 1);
                const int ty0 = (r >> 1) + (r & 1);
                float a0 = tv[ty0 * 4 + tx0];
                float a1 = tv[ty0 * 4 + tx0 + 1];
                float a2 = tv[(ty0 + 1) * 4 + tx0];
                float a3 = tv[(ty0 + 1) * 4 + tx0 + 1];
                float wx = swx[r * 4 + s][tid];
                float wy = swy[r * 4 + s][tid];
                float h0 = fmaf(wx, a1 - a0, a0);
                float h1 = fmaf(wx, a3 - a2, a2);
                vv[s] = fmaf(wy, h1 - h0, h0);
            }
            float4 v4 = make_float4(vv[0], vv[1], vv[2], vv[3]);
            *reinterpret_cast<float4*>(oc + (size_t)(ohb + r) * OW + owb) = v4;
        }
    }
}

extern "C" void kernel_launch(void* const* d_in, const int* in_sizes, int n_in,
                              void* d_out, int out_size) {
    const float* x    = (const float*)d_in[0];   // [8,256,80,80]
    const float* wq   = (const float*)d_in[1];   // [32,256,1,1]
    const float* bias = (const float*)d_in[2];   // [32]
    float* out = (float*)d_out;                  // [8,256,160,160]

    conv_off_kernel<<<400, 256>>>(x, wq, bias);
    sample_kernel<<<1600, 128>>>(x, out);
}